// round 11
// baseline (speedup 1.0000x reference)
#include <cuda_runtime.h>
#include <cuda_fp16.h>
#include <cstdint>

#define BATCH 64
#define TT    512
#define DD    512
#define HH    1024
#define MM    (BATCH * TT)        // 32768
#define KK    DD                  // 512
#define NN    HH                  // 1024

// ---------------- device scratch (no runtime alloc) ----------------
__device__ __half g_projh[3ULL * MM * NN];     // 192 MB fp16 projections
__device__ __half g_xh[(size_t)MM * KK];       // x fp16
__device__ __half g_wh[3ULL * NN * KK];        // weights^T fp16 [w][N][K]

__device__ __forceinline__ uint32_t smem_u32(const void* p) {
    uint32_t a;
    asm("{ .reg .u64 t; cvta.to.shared.u64 t, %1; cvt.u32.u64 %0, t; }" : "=r"(a) : "l"(p));
    return a;
}

#define CP16(sa, gp) asm volatile("cp.async.cg.shared.global [%0], [%1], 16;" :: "r"(sa), "l"(gp))
#define CP_COMMIT()  asm volatile("cp.async.commit_group;" ::: "memory")
#define CP_WAIT(n)   asm volatile("cp.async.wait_group %0;" :: "n"(n) : "memory")

__device__ __forceinline__ void ldm_x4(uint32_t a, uint32_t& r0, uint32_t& r1, uint32_t& r2, uint32_t& r3) {
    asm volatile("ldmatrix.sync.aligned.m8n8.x4.shared.b16 {%0,%1,%2,%3}, [%4];"
                 : "=r"(r0), "=r"(r1), "=r"(r2), "=r"(r3) : "r"(a));
}
__device__ __forceinline__ void mma_fp16(float* d, const uint32_t* a, const uint32_t* b) {
    asm volatile("mma.sync.aligned.m16n8k16.row.col.f32.f16.f16.f32 "
                 "{%0,%1,%2,%3}, {%4,%5,%6,%7}, {%8,%9}, {%0,%1,%2,%3};"
                 : "+f"(d[0]), "+f"(d[1]), "+f"(d[2]), "+f"(d[3])
                 : "r"(a[0]), "r"(a[1]), "r"(a[2]), "r"(a[3]), "r"(b[0]), "r"(b[1]));
}

// ---------------- prep: x -> fp16 ----------------
__global__ __launch_bounds__(256) void prep_x(const float* __restrict__ x) {
    size_t i = (size_t)blockIdx.x * 256 + threadIdx.x;
    if (i >= (size_t)MM * KK / 4) return;
    float4 v = ((const float4*)x)[i];
    __half2* o = (__half2*)g_xh;
    o[2 * i]     = __floats2half2_rn(v.x, v.y);
    o[2 * i + 1] = __floats2half2_rn(v.z, v.w);
}

// ---------------- prep: coalesced tiled transpose, W[k][n] -> g_wh[w][n][k] ----------------
__global__ __launch_bounds__(256) void prep_w(const float* __restrict__ kz,
                                              const float* __restrict__ kr,
                                              const float* __restrict__ kh) {
    __shared__ float tile[32][33];
    const int w  = blockIdx.z;
    const int k0 = blockIdx.x * 32;
    const int n0 = blockIdx.y * 32;
    const int tx = threadIdx.x;
    const int ty = threadIdx.y;
    const float* W = (w == 0) ? kz : (w == 1) ? kr : kh;

#pragma unroll
    for (int i = 0; i < 4; i++) {
        int k = k0 + ty + i * 8;
        tile[ty + i * 8][tx] = W[(size_t)k * NN + n0 + tx];
    }
    __syncthreads();
#pragma unroll
    for (int i = 0; i < 4; i++) {
        int n = n0 + ty + i * 8;
        g_wh[((size_t)w * NN + n) * KK + k0 + tx] = __float2half_rn(tile[tx][ty + i * 8]);
    }
}

// ---------------- mma.sync fp16 GEMM: CTA 128x256, warp tile 64x64 ----------------
// 8 warps (2 M x 4 N), 256 threads, K chunks of 64, 3-stage cp.async.
// SMEM row stride 144B (conflict-free for ldmatrix).
#define ROWB 144
#define A_BYTES (128 * ROWB)                     // 18432
#define B_BYTES (256 * ROWB)                     // 36864
#define STAGE_BYTES (A_BYTES + B_BYTES)          // 55296
#define NSTAGE 3
#define GEMM_SMEM (NSTAGE * STAGE_BYTES)         // 165888
#define KC 64
#define NCHUNK (KK / KC)                         // 8

__global__ __launch_bounds__(256, 1) void gemm_mma() {
    extern __shared__ char smem[];
    const uint32_t sb = smem_u32(smem);

    const int tid = threadIdx.x;
    const int wid = tid >> 5;
    const int lid = tid & 31;
    const int bn = blockIdx.x * 256;
    const int bm = blockIdx.y * 128;
    const int w  = blockIdx.z;
    const int warp_m = wid & 1;      // 0..1 -> 64-row band
    const int warp_n = wid >> 1;     // 0..3 -> 64-col band

    const __half* A = g_xh;
    const __half* B = g_wh + (size_t)w * NN * KK;
    __half* Cp = g_projh + (size_t)w * MM * NN;

    // loader: A 1024 + B 2048 16B-units, 256 threads -> 12 CP16/thread
    auto load_stage = [&](int chunk, int s) {
        const int k0 = chunk * KC;
        const uint32_t st = sb + s * STAGE_BYTES;
#pragma unroll
        for (int i = 0; i < 4; i++) {
            const int u = tid + i * 256;           // 0..1023 (A)
            const int r = u >> 3;
            const int c16 = u & 7;
            CP16(st + (uint32_t)(r * ROWB + c16 * 16),
                 A + (size_t)(bm + r) * KK + k0 + c16 * 8);
        }
#pragma unroll
        for (int i = 0; i < 8; i++) {
            const int v = tid + i * 256;           // 0..2047 (B)
            const int r = v >> 3;
            const int c16 = v & 7;
            CP16(st + A_BYTES + (uint32_t)(r * ROWB + c16 * 16),
                 B + (size_t)(bn + r) * KK + k0 + c16 * 8);
        }
    };

    const int a_r = (lid & 7) + ((lid >> 3) & 1) * 8;
    const int a_c = (lid >> 4) * 16;
    const int b_r = (lid & 7) + ((lid >> 4) ? 8 : 0);
    const int b_c = ((lid >> 3) & 1) * 16;
    const uint32_t aRow = (uint32_t)((warp_m * 64 + a_r) * ROWB + a_c);
    const uint32_t bRow = (uint32_t)((warp_n * 64 + b_r) * ROWB + b_c);

    float acc[4][8][4];
#pragma unroll
    for (int i = 0; i < 4; i++)
#pragma unroll
        for (int j = 0; j < 8; j++)
#pragma unroll
            for (int q = 0; q < 4; q++) acc[i][j][q] = 0.0f;

    load_stage(0, 0); CP_COMMIT();
    load_stage(1, 1); CP_COMMIT();

    for (int c = 0; c < NCHUNK; c++) {
        if (c + 2 < NCHUNK) CP_WAIT(1);
        else                CP_WAIT(0);
        __syncthreads();
        if (c + 2 < NCHUNK) { load_stage(c + 2, (c + 2) % NSTAGE); CP_COMMIT(); }

        const uint32_t st = sb + (c % NSTAGE) * STAGE_BYTES;
        const uint32_t aB = st + aRow;
        const uint32_t bB = st + A_BYTES + bRow;

#pragma unroll
        for (int kq = 0; kq < 4; kq++) {
            const uint32_t ko = kq * 32;
            uint32_t ah[4][4], bf[8][2];
#pragma unroll
            for (int mt = 0; mt < 4; mt++)
                ldm_x4(aB + mt * (16 * ROWB) + ko, ah[mt][0], ah[mt][1], ah[mt][2], ah[mt][3]);
#pragma unroll
            for (int np = 0; np < 4; np++) {
                uint32_t r0, r1, r2, r3;
                ldm_x4(bB + np * (16 * ROWB) + ko, r0, r1, r2, r3);
                bf[2 * np][0] = r0;     bf[2 * np][1] = r1;
                bf[2 * np + 1][0] = r2; bf[2 * np + 1][1] = r3;
            }
#pragma unroll
            for (int mt = 0; mt < 4; mt++)
#pragma unroll
                for (int nt = 0; nt < 8; nt++)
                    mma_fp16(acc[mt][nt], ah[mt], bf[nt]);
        }
    }

    // epilogue: fp16 stores
    const int er = lid >> 2;
    const int ec = (lid & 3) * 2;
#pragma unroll
    for (int mt = 0; mt < 4; mt++) {
        const int row = bm + warp_m * 64 + mt * 16 + er;
#pragma unroll
        for (int nt = 0; nt < 8; nt++) {
            const int col = bn + warp_n * 64 + nt * 8 + ec;
            *(__half2*)(Cp + (size_t)row * NN + col) =
                __floats2half2_rn(acc[mt][nt][0], acc[mt][nt][1]);
            *(__half2*)(Cp + (size_t)(row + 8) * NN + col) =
                __floats2half2_rn(acc[mt][nt][2], acc[mt][nt][3]);
        }
    }
}

// ---------------- recurrence scan: R9 step, DEPTH-16 ring ----------------
__device__ __forceinline__ float tanh_fast(float x) {
    float y;
    asm("tanh.approx.f32 %0, %1;" : "=f"(y) : "f"(x));
    return y;
}
__device__ __forceinline__ float brc_step(float xz, float xr, float xh,
                                          float h, float mzv, float mrv,
                                          float bzv, float brv) {
    float r = tanh_fast(fmaf(h, mrv, xr + brv)) + 1.0f;
    float z = fmaf(tanh_fast(0.5f * fmaf(h, mzv, xz + bzv)), 0.5f, 0.5f);
    float c = tanh_fast(fmaf(r, h, xh));
    return fmaf(z, h - c, c);
}

#define DEPTH 16
#define H2C (HH / 2)    // 512 half2 per row

__global__ __launch_bounds__(64) void scan_kernel(
    const float* __restrict__ mz, const float* __restrict__ mr,
    const float* __restrict__ br, const float* __restrict__ bz,
    float* __restrict__ out) {
    const int ch2 = blockIdx.x * 64 + threadIdx.x;   // 0..32767
    const int b  = ch2 >> 9;
    const int h2 = ch2 & (H2C - 1);

    const float2 mzv = ((const float2*)mz)[h2];
    const float2 mrv = ((const float2*)mr)[h2];
    const float2 brv = ((const float2*)br)[h2];
    const float2 bzv = ((const float2*)bz)[h2];

    const size_t base = (size_t)b * TT * HH + (size_t)h2 * 2;
    const size_t PLANE = (size_t)MM * NN;
    const __half2* pz = (const __half2*)(g_projh + 0 * PLANE + base);
    const __half2* pr = (const __half2*)(g_projh + 1 * PLANE + base);
    const __half2* ph = (const __half2*)(g_projh + 2 * PLANE + base);
    float2* po = (float2*)(out + base);

    float2 hs = make_float2(0.0f, 0.0f);
    __half2 zb[DEPTH], rb[DEPTH], hb[DEPTH];
#pragma unroll
    for (int s = 0; s < DEPTH; s++) {
        size_t o = (size_t)s * H2C;
        zb[s] = pz[o]; rb[s] = pr[o]; hb[s] = ph[o];
    }

#pragma unroll 16
    for (int t = 0; t < TT; t++) {
        const int s = t & (DEPTH - 1);
        float2 xz0 = __half22float2(zb[s]);
        float2 xr0 = __half22float2(rb[s]);
        float2 xh0 = __half22float2(hb[s]);
        if (t + DEPTH < TT) {
            size_t o = (size_t)(t + DEPTH) * H2C;
            zb[s] = pz[o]; rb[s] = pr[o]; hb[s] = ph[o];
        }
        hs.x = brc_step(xz0.x, xr0.x, xh0.x, hs.x, mzv.x, mrv.x, bzv.x, brv.x);
        hs.y = brc_step(xz0.y, xr0.y, xh0.y, hs.y, mzv.y, mrv.y, bzv.y, brv.y);
        po[(size_t)t * H2C] = hs;
    }
}

// ---------------- launch ----------------
extern "C" void kernel_launch(void* const* d_in, const int* in_sizes, int n_in,
                              void* d_out, int out_size) {
    const float* x  = (const float*)d_in[0];
    const float* kz = (const float*)d_in[1];
    const float* kr = (const float*)d_in[2];
    const float* kh = (const float*)d_in[3];
    const float* mz = (const float*)d_in[4];
    const float* mr = (const float*)d_in[5];
    const float* br = (const float*)d_in[6];
    const float* bz = (const float*)d_in[7];
    float* out = (float*)d_out;

    cudaFuncSetAttribute(gemm_mma, cudaFuncAttributeMaxDynamicSharedMemorySize, GEMM_SMEM);

    prep_x<<<(MM * KK / 4 + 255) / 256, 256>>>(x);
    {
        dim3 wgrid(KK / 32, NN / 32, 3);
        dim3 wblk(32, 8, 1);
        prep_w<<<wgrid, wblk>>>(kz, kr, kh);
    }

    dim3 ggrid(NN / 256, MM / 128, 3);   // (4, 256, 3)
    gemm_mma<<<ggrid, 256, GEMM_SMEM>>>();

    scan_kernel<<<(BATCH * HH / 2) / 64, 64>>>(mz, mr, br, bz, out);
}

// round 12
// speedup vs baseline: 1.1007x; 1.1007x over previous
#include <cuda_runtime.h>
#include <cuda_fp16.h>
#include <cstdint>

#define BATCH 64
#define TT    512
#define DD    512
#define HH    1024
#define MM    (BATCH * TT)        // 32768
#define KK    DD                  // 512
#define NN    HH                  // 1024

// ---------------- device scratch (no runtime alloc) ----------------
__device__ __half g_projh[3ULL * MM * NN];     // 192 MB fp16 projections
__device__ __half g_xh[(size_t)MM * KK];       // x fp16
__device__ __half g_wh[3ULL * NN * KK];        // weights^T fp16 [w][N][K]

__device__ __forceinline__ uint32_t smem_u32(const void* p) {
    uint32_t a;
    asm("{ .reg .u64 t; cvta.to.shared.u64 t, %1; cvt.u32.u64 %0, t; }" : "=r"(a) : "l"(p));
    return a;
}

#define CP16(sa, gp) asm volatile("cp.async.cg.shared.global [%0], [%1], 16;" :: "r"(sa), "l"(gp))
#define CP_COMMIT()  asm volatile("cp.async.commit_group;" ::: "memory")
#define CP_WAIT(n)   asm volatile("cp.async.wait_group %0;" :: "n"(n) : "memory")

__device__ __forceinline__ void ldm_x4(uint32_t a, uint32_t& r0, uint32_t& r1, uint32_t& r2, uint32_t& r3) {
    asm volatile("ldmatrix.sync.aligned.m8n8.x4.shared.b16 {%0,%1,%2,%3}, [%4];"
                 : "=r"(r0), "=r"(r1), "=r"(r2), "=r"(r3) : "r"(a));
}
__device__ __forceinline__ void mma_fp16(float* d, const uint32_t* a, const uint32_t* b) {
    asm volatile("mma.sync.aligned.m16n8k16.row.col.f32.f16.f16.f32 "
                 "{%0,%1,%2,%3}, {%4,%5,%6,%7}, {%8,%9}, {%0,%1,%2,%3};"
                 : "+f"(d[0]), "+f"(d[1]), "+f"(d[2]), "+f"(d[3])
                 : "r"(a[0]), "r"(a[1]), "r"(a[2]), "r"(a[3]), "r"(b[0]), "r"(b[1]));
}

// ---------------- prep: x -> fp16 ----------------
__global__ __launch_bounds__(256) void prep_x(const float* __restrict__ x) {
    size_t i = (size_t)blockIdx.x * 256 + threadIdx.x;
    if (i >= (size_t)MM * KK / 4) return;
    float4 v = ((const float4*)x)[i];
    __half2* o = (__half2*)g_xh;
    o[2 * i]     = __floats2half2_rn(v.x, v.y);
    o[2 * i + 1] = __floats2half2_rn(v.z, v.w);
}

// ---------------- prep: coalesced tiled transpose, W[k][n] -> g_wh[w][n][k] ----------------
__global__ __launch_bounds__(256) void prep_w(const float* __restrict__ kz,
                                              const float* __restrict__ kr,
                                              const float* __restrict__ kh) {
    __shared__ float tile[32][33];
    const int w  = blockIdx.z;
    const int k0 = blockIdx.x * 32;
    const int n0 = blockIdx.y * 32;
    const int tx = threadIdx.x;
    const int ty = threadIdx.y;
    const float* W = (w == 0) ? kz : (w == 1) ? kr : kh;

#pragma unroll
    for (int i = 0; i < 4; i++) {
        int k = k0 + ty + i * 8;
        tile[ty + i * 8][tx] = W[(size_t)k * NN + n0 + tx];
    }
    __syncthreads();
#pragma unroll
    for (int i = 0; i < 4; i++) {
        int n = n0 + ty + i * 8;
        g_wh[((size_t)w * NN + n) * KK + k0 + tx] = __float2half_rn(tile[tx][ty + i * 8]);
    }
}

// ---------------- mma.sync fp16 GEMM (R9 config): CTA 128x128, 8 warps ----------------
// warp tile 32x64 (warp_m = wid&3, warp_n = wid>>2). K chunks of 64, 3-stage cp.async.
// SMEM row stride 144B (conflict-free for ldmatrix).
#define ROWB 144
#define TILE_BYTES (128 * ROWB)                  // 18432
#define STAGE_BYTES (2 * TILE_BYTES)             // 36864
#define NSTAGE 3
#define GEMM_SMEM (NSTAGE * STAGE_BYTES)         // 110592
#define KC 64
#define NCHUNK (KK / KC)                         // 8

__global__ __launch_bounds__(256, 2) void gemm_mma() {
    extern __shared__ char smem[];
    const uint32_t sb = smem_u32(smem);

    const int tid = threadIdx.x;
    const int wid = tid >> 5;
    const int lid = tid & 31;
    const int bn = blockIdx.x * 128;
    const int bm = blockIdx.y * 128;
    const int w  = blockIdx.z;
    const int warp_m = wid & 3;
    const int warp_n = wid >> 2;

    const __half* A = g_xh;
    const __half* B = g_wh + (size_t)w * NN * KK;
    __half* Cp = g_projh + (size_t)w * MM * NN;

    auto load_stage = [&](int chunk, int s) {
        const int k0 = chunk * KC;
        const uint32_t st = sb + s * STAGE_BYTES;
#pragma unroll
        for (int i = 0; i < 4; i++) {
            const int u = tid + i * 256;
            const int r = u >> 3;
            const int c16 = u & 7;
            const uint32_t so = (uint32_t)(r * ROWB + c16 * 16);
            CP16(st + so,              A + (size_t)(bm + r) * KK + k0 + c16 * 8);
            CP16(st + TILE_BYTES + so, B + (size_t)(bn + r) * KK + k0 + c16 * 8);
        }
    };

    const int a_r = (lid & 7) + ((lid >> 3) & 1) * 8;
    const int a_c = (lid >> 4) * 16;
    const int b_r = (lid & 7) + ((lid >> 4) ? 8 : 0);
    const int b_c = ((lid >> 3) & 1) * 16;
    const uint32_t aRow = (uint32_t)((warp_m * 32 + a_r) * ROWB + a_c);
    const uint32_t bRow = (uint32_t)((warp_n * 64 + b_r) * ROWB + b_c);

    float acc[2][8][4];
#pragma unroll
    for (int i = 0; i < 2; i++)
#pragma unroll
        for (int j = 0; j < 8; j++)
#pragma unroll
            for (int q = 0; q < 4; q++) acc[i][j][q] = 0.0f;

    load_stage(0, 0); CP_COMMIT();
    load_stage(1, 1); CP_COMMIT();

    for (int c = 0; c < NCHUNK; c++) {
        if (c + 2 < NCHUNK) CP_WAIT(1);
        else                CP_WAIT(0);
        __syncthreads();
        if (c + 2 < NCHUNK) { load_stage(c + 2, (c + 2) % NSTAGE); CP_COMMIT(); }

        const uint32_t st = sb + (c % NSTAGE) * STAGE_BYTES;
        const uint32_t aB = st + aRow;
        const uint32_t bB = st + TILE_BYTES + bRow;

#pragma unroll
        for (int kq = 0; kq < 4; kq++) {
            const uint32_t ko = kq * 32;
            uint32_t ah[2][4], bf[8][2];
#pragma unroll
            for (int mt = 0; mt < 2; mt++)
                ldm_x4(aB + mt * (16 * ROWB) + ko, ah[mt][0], ah[mt][1], ah[mt][2], ah[mt][3]);
#pragma unroll
            for (int np = 0; np < 4; np++) {
                uint32_t r0, r1, r2, r3;
                ldm_x4(bB + np * (16 * ROWB) + ko, r0, r1, r2, r3);
                bf[2 * np][0] = r0;     bf[2 * np][1] = r1;
                bf[2 * np + 1][0] = r2; bf[2 * np + 1][1] = r3;
            }
#pragma unroll
            for (int mt = 0; mt < 2; mt++)
#pragma unroll
                for (int nt = 0; nt < 8; nt++)
                    mma_fp16(acc[mt][nt], ah[mt], bf[nt]);
        }
    }

    // epilogue: fp16 stores
    const int er = lid >> 2;
    const int ec = (lid & 3) * 2;
#pragma unroll
    for (int mt = 0; mt < 2; mt++) {
        const int row = bm + warp_m * 32 + mt * 16 + er;
#pragma unroll
        for (int nt = 0; nt < 8; nt++) {
            const int col = bn + warp_n * 64 + nt * 8 + ec;
            *(__half2*)(Cp + (size_t)row * NN + col) =
                __floats2half2_rn(acc[mt][nt][0], acc[mt][nt][1]);
            *(__half2*)(Cp + (size_t)(row + 8) * NN + col) =
                __floats2half2_rn(acc[mt][nt][2], acc[mt][nt][3]);
        }
    }
}

// ---------------- recurrence scan: 2 ch/thread half2, DEPTH-16 ring ----------------
__device__ __forceinline__ float tanh_fast(float x) {
    float y;
    asm("tanh.approx.f32 %0, %1;" : "=f"(y) : "f"(x));
    return y;
}
__device__ __forceinline__ float brc_step(float xz, float xr, float xh,
                                          float h, float mzv, float mrv,
                                          float bzv, float brv) {
    float r = tanh_fast(fmaf(h, mrv, xr + brv)) + 1.0f;
    float z = fmaf(tanh_fast(0.5f * fmaf(h, mzv, xz + bzv)), 0.5f, 0.5f);
    float c = tanh_fast(fmaf(r, h, xh));
    return fmaf(z, h - c, c);
}

#define DEPTH 16
#define H2C (HH / 2)    // 512 half2 per row

__global__ __launch_bounds__(64) void scan_kernel(
    const float* __restrict__ mz, const float* __restrict__ mr,
    const float* __restrict__ br, const float* __restrict__ bz,
    float* __restrict__ out) {
    const int ch2 = blockIdx.x * 64 + threadIdx.x;   // 0..32767
    const int b  = ch2 >> 9;
    const int h2 = ch2 & (H2C - 1);

    const float2 mzv = ((const float2*)mz)[h2];
    const float2 mrv = ((const float2*)mr)[h2];
    const float2 brv = ((const float2*)br)[h2];
    const float2 bzv = ((const float2*)bz)[h2];

    const size_t base = (size_t)b * TT * HH + (size_t)h2 * 2;
    const size_t PLANE = (size_t)MM * NN;
    const __half2* pz = (const __half2*)(g_projh + 0 * PLANE + base);
    const __half2* pr = (const __half2*)(g_projh + 1 * PLANE + base);
    const __half2* ph = (const __half2*)(g_projh + 2 * PLANE + base);
    float2* po = (float2*)(out + base);

    float2 hs = make_float2(0.0f, 0.0f);
    __half2 zb[DEPTH], rb[DEPTH], hb[DEPTH];
#pragma unroll
    for (int s = 0; s < DEPTH; s++) {
        size_t o = (size_t)s * H2C;
        zb[s] = pz[o]; rb[s] = pr[o]; hb[s] = ph[o];
    }

#pragma unroll 16
    for (int t = 0; t < TT; t++) {
        const int s = t & (DEPTH - 1);
        float2 xz0 = __half22float2(zb[s]);
        float2 xr0 = __half22float2(rb[s]);
        float2 xh0 = __half22float2(hb[s]);
        if (t + DEPTH < TT) {
            size_t o = (size_t)(t + DEPTH) * H2C;
            zb[s] = pz[o]; rb[s] = pr[o]; hb[s] = ph[o];
        }
        hs.x = brc_step(xz0.x, xr0.x, xh0.x, hs.x, mzv.x, mrv.x, bzv.x, brv.x);
        hs.y = brc_step(xz0.y, xr0.y, xh0.y, hs.y, mzv.y, mrv.y, bzv.y, brv.y);
        po[(size_t)t * H2C] = hs;
    }
}

// ---------------- launch ----------------
extern "C" void kernel_launch(void* const* d_in, const int* in_sizes, int n_in,
                              void* d_out, int out_size) {
    const float* x  = (const float*)d_in[0];
    const float* kz = (const float*)d_in[1];
    const float* kr = (const float*)d_in[2];
    const float* kh = (const float*)d_in[3];
    const float* mz = (const float*)d_in[4];
    const float* mr = (const float*)d_in[5];
    const float* br = (const float*)d_in[6];
    const float* bz = (const float*)d_in[7];
    float* out = (float*)d_out;

    cudaFuncSetAttribute(gemm_mma, cudaFuncAttributeMaxDynamicSharedMemorySize, GEMM_SMEM);

    prep_x<<<(MM * KK / 4 + 255) / 256, 256>>>(x);
    {
        dim3 wgrid(KK / 32, NN / 32, 3);
        dim3 wblk(32, 8, 1);
        prep_w<<<wgrid, wblk>>>(kz, kr, kh);
    }

    dim3 ggrid(NN / 128, MM / 128, 3);   // (8, 256, 3)
    gemm_mma<<<ggrid, 256, GEMM_SMEM>>>();

    scan_kernel<<<(BATCH * HH / 2) / 64, 64>>>(mz, mr, br, bz, out);
}

// round 13
// speedup vs baseline: 1.1064x; 1.0052x over previous
#include <cuda_runtime.h>
#include <cuda_fp16.h>
#include <cstdint>

#define BATCH 64
#define TT    512
#define DD    512
#define HH    1024
#define MM    (BATCH * TT)        // 32768
#define KK    DD                  // 512
#define NN    HH                  // 1024

// ---------------- device scratch (no runtime alloc) ----------------
__device__ __half g_projh[3ULL * MM * NN];     // 192 MB fp16 projections
__device__ __half g_xh[(size_t)MM * KK];       // x fp16
__device__ __half g_wh[3ULL * NN * KK];        // weights^T fp16 [w][N][K]

__device__ __forceinline__ uint32_t smem_u32(const void* p) {
    uint32_t a;
    asm("{ .reg .u64 t; cvta.to.shared.u64 t, %1; cvt.u32.u64 %0, t; }" : "=r"(a) : "l"(p));
    return a;
}

#define CP16(sa, gp) asm volatile("cp.async.cg.shared.global [%0], [%1], 16;" :: "r"(sa), "l"(gp))
#define CP_COMMIT()  asm volatile("cp.async.commit_group;" ::: "memory")
#define CP_WAIT(n)   asm volatile("cp.async.wait_group %0;" :: "n"(n) : "memory")

__device__ __forceinline__ void ldm_x4(uint32_t a, uint32_t& r0, uint32_t& r1, uint32_t& r2, uint32_t& r3) {
    asm volatile("ldmatrix.sync.aligned.m8n8.x4.shared.b16 {%0,%1,%2,%3}, [%4];"
                 : "=r"(r0), "=r"(r1), "=r"(r2), "=r"(r3) : "r"(a));
}
__device__ __forceinline__ void mma_fp16(float* d, const uint32_t* a, const uint32_t* b) {
    asm volatile("mma.sync.aligned.m16n8k16.row.col.f32.f16.f16.f32 "
                 "{%0,%1,%2,%3}, {%4,%5,%6,%7}, {%8,%9}, {%0,%1,%2,%3};"
                 : "+f"(d[0]), "+f"(d[1]), "+f"(d[2]), "+f"(d[3])
                 : "r"(a[0]), "r"(a[1]), "r"(a[2]), "r"(a[3]), "r"(b[0]), "r"(b[1]));
}

// ---------------- fused prep: x -> fp16  +  W transpose -> fp16 ----------------
// blocks [0, NXB): x conversion. blocks [NXB, NXB+NWB): tiled W transpose.
#define NXB (MM * KK / 4 / 256)          // 16384
#define NWB (3 * (KK / 32) * (NN / 32))  // 1536

__global__ __launch_bounds__(256) void prep_all(const float* __restrict__ x,
                                                const float* __restrict__ kz,
                                                const float* __restrict__ kr,
                                                const float* __restrict__ kh) {
    __shared__ float tile[32][33];
    const int bid = blockIdx.x;
    const int tid = threadIdx.x;

    if (bid < NXB) {
        size_t i = (size_t)bid * 256 + tid;
        float4 v = ((const float4*)x)[i];
        __half2* o = (__half2*)g_xh;
        o[2 * i]     = __floats2half2_rn(v.x, v.y);
        o[2 * i + 1] = __floats2half2_rn(v.z, v.w);
        return;
    }

    const int b2 = bid - NXB;                 // 0..1535
    const int w  = b2 / ((KK / 32) * (NN / 32));
    const int rem = b2 % ((KK / 32) * (NN / 32));
    const int k0 = (rem % (KK / 32)) * 32;
    const int n0 = (rem / (KK / 32)) * 32;
    const int tx = tid & 31;
    const int ty = tid >> 5;
    const float* W = (w == 0) ? kz : (w == 1) ? kr : kh;

#pragma unroll
    for (int i = 0; i < 4; i++) {
        int k = k0 + ty + i * 8;
        tile[ty + i * 8][tx] = W[(size_t)k * NN + n0 + tx];
    }
    __syncthreads();
#pragma unroll
    for (int i = 0; i < 4; i++) {
        int n = n0 + ty + i * 8;
        g_wh[((size_t)w * NN + n) * KK + k0 + tx] = __float2half_rn(tile[tx][ty + i * 8]);
    }
}

// ---------------- mma.sync fp16 GEMM (R9/R12 config): CTA 128x128, 8 warps ----------------
#define ROWB 144
#define TILE_BYTES (128 * ROWB)                  // 18432
#define STAGE_BYTES (2 * TILE_BYTES)             // 36864
#define NSTAGE 3
#define GEMM_SMEM (NSTAGE * STAGE_BYTES)         // 110592
#define KC 64
#define NCHUNK (KK / KC)                         // 8

__global__ __launch_bounds__(256, 2) void gemm_mma() {
    extern __shared__ char smem[];
    const uint32_t sb = smem_u32(smem);

    const int tid = threadIdx.x;
    const int wid = tid >> 5;
    const int lid = tid & 31;
    const int bn = blockIdx.x * 128;
    const int bm = blockIdx.y * 128;
    const int w  = blockIdx.z;
    const int warp_m = wid & 3;
    const int warp_n = wid >> 2;

    const __half* A = g_xh;
    const __half* B = g_wh + (size_t)w * NN * KK;
    __half* Cp = g_projh + (size_t)w * MM * NN;

    auto load_stage = [&](int chunk, int s) {
        const int k0 = chunk * KC;
        const uint32_t st = sb + s * STAGE_BYTES;
#pragma unroll
        for (int i = 0; i < 4; i++) {
            const int u = tid + i * 256;
            const int r = u >> 3;
            const int c16 = u & 7;
            const uint32_t so = (uint32_t)(r * ROWB + c16 * 16);
            CP16(st + so,              A + (size_t)(bm + r) * KK + k0 + c16 * 8);
            CP16(st + TILE_BYTES + so, B + (size_t)(bn + r) * KK + k0 + c16 * 8);
        }
    };

    const int a_r = (lid & 7) + ((lid >> 3) & 1) * 8;
    const int a_c = (lid >> 4) * 16;
    const int b_r = (lid & 7) + ((lid >> 4) ? 8 : 0);
    const int b_c = ((lid >> 3) & 1) * 16;
    const uint32_t aRow = (uint32_t)((warp_m * 32 + a_r) * ROWB + a_c);
    const uint32_t bRow = (uint32_t)((warp_n * 64 + b_r) * ROWB + b_c);

    float acc[2][8][4];
#pragma unroll
    for (int i = 0; i < 2; i++)
#pragma unroll
        for (int j = 0; j < 8; j++)
#pragma unroll
            for (int q = 0; q < 4; q++) acc[i][j][q] = 0.0f;

    load_stage(0, 0); CP_COMMIT();
    load_stage(1, 1); CP_COMMIT();

    for (int c = 0; c < NCHUNK; c++) {
        if (c + 2 < NCHUNK) CP_WAIT(1);
        else                CP_WAIT(0);
        __syncthreads();
        if (c + 2 < NCHUNK) { load_stage(c + 2, (c + 2) % NSTAGE); CP_COMMIT(); }

        const uint32_t st = sb + (c % NSTAGE) * STAGE_BYTES;
        const uint32_t aB = st + aRow;
        const uint32_t bB = st + TILE_BYTES + bRow;

#pragma unroll
        for (int kq = 0; kq < 4; kq++) {
            const uint32_t ko = kq * 32;
            uint32_t ah[2][4], bf[8][2];
#pragma unroll
            for (int mt = 0; mt < 2; mt++)
                ldm_x4(aB + mt * (16 * ROWB) + ko, ah[mt][0], ah[mt][1], ah[mt][2], ah[mt][3]);
#pragma unroll
            for (int np = 0; np < 4; np++) {
                uint32_t r0, r1, r2, r3;
                ldm_x4(bB + np * (16 * ROWB) + ko, r0, r1, r2, r3);
                bf[2 * np][0] = r0;     bf[2 * np][1] = r1;
                bf[2 * np + 1][0] = r2; bf[2 * np + 1][1] = r3;
            }
#pragma unroll
            for (int mt = 0; mt < 2; mt++)
#pragma unroll
                for (int nt = 0; nt < 8; nt++)
                    mma_fp16(acc[mt][nt], ah[mt], bf[nt]);
        }
    }

    const int er = lid >> 2;
    const int ec = (lid & 3) * 2;
#pragma unroll
    for (int mt = 0; mt < 2; mt++) {
        const int row = bm + warp_m * 32 + mt * 16 + er;
#pragma unroll
        for (int nt = 0; nt < 8; nt++) {
            const int col = bn + warp_n * 64 + nt * 8 + ec;
            *(__half2*)(Cp + (size_t)row * NN + col) =
                __floats2half2_rn(acc[mt][nt][0], acc[mt][nt][1]);
            *(__half2*)(Cp + (size_t)(row + 8) * NN + col) =
                __floats2half2_rn(acc[mt][nt][2], acc[mt][nt][3]);
        }
    }
}

// ---------------- recurrence scan: DEPTH-16 ring, nc loads / cs stores ----------------
__device__ __forceinline__ float tanh_fast(float x) {
    float y;
    asm("tanh.approx.f32 %0, %1;" : "=f"(y) : "f"(x));
    return y;
}
__device__ __forceinline__ float brc_step(float xz, float xr, float xh,
                                          float h, float mzv, float mrv,
                                          float bzv, float brv) {
    float r = tanh_fast(fmaf(h, mrv, xr + brv)) + 1.0f;
    float z = fmaf(tanh_fast(0.5f * fmaf(h, mzv, xz + bzv)), 0.5f, 0.5f);
    float c = tanh_fast(fmaf(r, h, xh));
    return fmaf(z, h - c, c);
}

__device__ __forceinline__ uint32_t ldnc_u32(const __half2* p) {
    uint32_t v;
    asm volatile("ld.global.nc.b32 %0, [%1];" : "=r"(v) : "l"(p));
    return v;
}
__device__ __forceinline__ void stcs_f2(float* p, float2 v) {
    asm volatile("st.global.cs.v2.f32 [%0], {%1, %2};" :: "l"(p), "f"(v.x), "f"(v.y));
}

#define DEPTH 16
#define H2C (HH / 2)    // 512 half2 per row

__global__ __launch_bounds__(64) void scan_kernel(
    const float* __restrict__ mz, const float* __restrict__ mr,
    const float* __restrict__ br, const float* __restrict__ bz,
    float* __restrict__ out) {
    const int ch2 = blockIdx.x * 64 + threadIdx.x;   // 0..32767
    const int b  = ch2 >> 9;
    const int h2 = ch2 & (H2C - 1);

    const float2 mzv = ((const float2*)mz)[h2];
    const float2 mrv = ((const float2*)mr)[h2];
    const float2 brv = ((const float2*)br)[h2];
    const float2 bzv = ((const float2*)bz)[h2];

    const size_t base = (size_t)b * TT * HH + (size_t)h2 * 2;
    const size_t PLANE = (size_t)MM * NN;
    const __half2* pz = (const __half2*)(g_projh + 0 * PLANE + base);
    const __half2* pr = (const __half2*)(g_projh + 1 * PLANE + base);
    const __half2* ph = (const __half2*)(g_projh + 2 * PLANE + base);
    float* po = out + base;

    float2 hs = make_float2(0.0f, 0.0f);
    uint32_t zb[DEPTH], rb[DEPTH], hb[DEPTH];
#pragma unroll
    for (int s = 0; s < DEPTH; s++) {
        size_t o = (size_t)s * H2C;
        zb[s] = ldnc_u32(pz + o); rb[s] = ldnc_u32(pr + o); hb[s] = ldnc_u32(ph + o);
    }

#pragma unroll 16
    for (int t = 0; t < TT; t++) {
        const int s = t & (DEPTH - 1);
        float2 xz0 = __half22float2(*(const __half2*)&zb[s]);
        float2 xr0 = __half22float2(*(const __half2*)&rb[s]);
        float2 xh0 = __half22float2(*(const __half2*)&hb[s]);
        if (t + DEPTH < TT) {
            size_t o = (size_t)(t + DEPTH) * H2C;
            zb[s] = ldnc_u32(pz + o); rb[s] = ldnc_u32(pr + o); hb[s] = ldnc_u32(ph + o);
        }
        hs.x = brc_step(xz0.x, xr0.x, xh0.x, hs.x, mzv.x, mrv.x, bzv.x, brv.x);
        hs.y = brc_step(xz0.y, xr0.y, xh0.y, hs.y, mzv.y, mrv.y, bzv.y, brv.y);
        stcs_f2(po + (size_t)t * HH, hs);
    }
}

// ---------------- launch ----------------
extern "C" void kernel_launch(void* const* d_in, const int* in_sizes, int n_in,
                              void* d_out, int out_size) {
    const float* x  = (const float*)d_in[0];
    const float* kz = (const float*)d_in[1];
    const float* kr = (const float*)d_in[2];
    const float* kh = (const float*)d_in[3];
    const float* mz = (const float*)d_in[4];
    const float* mr = (const float*)d_in[5];
    const float* br = (const float*)d_in[6];
    const float* bz = (const float*)d_in[7];
    float* out = (float*)d_out;

    cudaFuncSetAttribute(gemm_mma, cudaFuncAttributeMaxDynamicSharedMemorySize, GEMM_SMEM);

    prep_all<<<NXB + NWB, 256>>>(x, kz, kr, kh);

    dim3 ggrid(NN / 128, MM / 128, 3);   // (8, 256, 3)
    gemm_mma<<<ggrid, 256, GEMM_SMEM>>>();

    scan_kernel<<<(BATCH * HH / 2) / 64, 64>>>(mz, mr, br, bz, out);
}